// round 8
// baseline (speedup 1.0000x reference)
#include <cuda_runtime.h>
#include <math.h>

#define FULL_MASK 0xffffffffu

constexpr int HW = 256;   // 16x16 grid -> scan length
constexpr int B  = 1024;

// f32 ops with explicit FTZ semantics (flush denormal inputs/outputs),
// independent of nvcc flags. These emulate the reference's XLA-GPU f32 pipeline.
__device__ __forceinline__ float fmul_ftz(float a, float b) {
    float r; asm("mul.rn.ftz.f32 %0,%1,%2;" : "=f"(r) : "f"(a), "f"(b)); return r;
}
__device__ __forceinline__ float fadd_ftz(float a, float b) {
    float r; asm("add.rn.ftz.f32 %0,%1,%2;" : "=f"(r) : "f"(a), "f"(b)); return r;
}
__device__ __forceinline__ float fsub_ftz(float a, float b) {
    float r; asm("sub.rn.ftz.f32 %0,%1,%2;" : "=f"(r) : "f"(a), "f"(b)); return r;
}
__device__ __forceinline__ float fdiv_ftz(float a, float b) {
    float r; asm("div.rn.ftz.f32 %0,%1,%2;" : "=f"(r) : "f"(a), "f"(b)); return r;
}

// One warp per batch row. Count support j in [0,64): lane L holds j=L (cd0)
// and j=L+32 (cd1). Init is zero for j >= 42 (p^42 = 2^-128.9 dies in the
// reference's approx-pow lowering); everything else evolves under faithful
// f32-FTZ dynamics, so tail elements flush exactly when the reference's do.
// Once the live support's max j <= csf, p_z == 0 forever (closed-form path).
__global__ __launch_bounds__(32)
void obj_kl_kernel(const float* __restrict__ z_pres,
                   const float* __restrict__ z_prob,
                   float* __restrict__ out)
{
    const int b    = blockIdx.x;
    const int lane = threadIdx.x;

    const float* pr = z_prob + b * HW;
    const float* zs = z_pres + b * HW;
    float*       op = out    + b * HW;

    // p in f32 exactly as the reference: 1/(exp(2f)+1)
    const float  e2p1 = 7.3890560989306495f + 1.0f;      // f32(e^2)+1
    const float  pf   = __fdiv_rn(1.0f, e2p1);
    const double pd   = (double)pf;

    // (1-p)p^lane and (1-p)p^(lane+32), correctly rounded via f64 binary exp.
    double pp = 1.0, ps = pd;
    int e = lane;
#pragma unroll
    for (int k = 0; k < 5; ++k) { if (e & 1) pp *= ps; ps *= ps; e >>= 1; }
    const double omp = 1.0 - pd;
    float cd0 = (float)(omp * pp);                        // j = lane (normal range)
    float cd1 = (lane <= 9) ? (float)(omp * pp * ps)      // j = lane+32, j <= 41
                            : 0.0f;

    // Faithful init normalization: cd0 / cd0.sum() in f32.
    {
        float S = fadd_ftz(cd0, cd1);
#pragma unroll
        for (int m = 16; m > 0; m >>= 1)
            S = fadd_ftz(S, __shfl_xor_sync(FULL_MASK, S, m));
        cd0 = fdiv_ftz(cd0, S);
        cd1 = fdiv_ftz(cd1, S);
    }

    int csf = 0;                       // count_so_far (integer, exact)
    const float EPSF   = 1e-9f;
    const float LOGEPS = __logf(1e-9f);

#pragma unroll 1
    for (int c = 0; c < 8; ++c) {
        const float myp = pr[c * 32 + lane];

        // Dynamic death check: highest j with cd != 0.
        const unsigned b0 = __ballot_sync(FULL_MASK, cd0 != 0.0f);
        const unsigned b1 = __ballot_sync(FULL_MASK, cd1 != 0.0f);
        const int maxj = b1 ? (63 - __clz(b1)) : (b0 ? (31 - __clz(b0)) : -1);

        if (maxj <= csf) {
            // p_z == 0 exactly for every remaining step:
            // kl = prob*(log(prob+e) - log(e)) + (1-prob)*log(1-prob+e)
            const float l1 = __logf(myp + EPSF);
            const float l0 = __logf((1.0f - myp) + EPSF);
            op[c * 32 + lane] = myp * (l1 - LOGEPS) + (1.0f - myp) * l0;
            continue;
        }

        const float myz = zs[c * 32 + lane];
        float mykl = 0.0f;

#pragma unroll
        for (int s = 0; s < 32; ++s) {
            const int   i     = c * 32 + s;
            const float prob  = __shfl_sync(FULL_MASK, myp, s);
            const float zp    = __shfl_sync(FULL_MASK, myz, s);
            const int   denom = HW - i;
            const float denf  = (float)denom;
            const bool  s1    = (rintf(zp) != 0.0f);   // sample in {0,1}

            // p(z=1|C) numerator clamp in exact ints, then f32 division
            const int t0 = min(max(lane      - csf, 0), denom);
            const int t1 = min(max(lane + 32 - csf, 0), denom);
            const float pzg0 = fdiv_ftz((float)t0, denf);
            const float pzg1 = fdiv_ftz((float)t1, denf);

            // q = cd * pzg  (flushes exactly like the reference's products)
            const float q0 = fmul_ftz(cd0, pzg0);
            const float q1 = fmul_ftz(cd1, pzg1);

            // n = cd * mult, mult = sample?pzg:(1-pzg) (1-pzg rounded first)
            float n0, n1;
            if (s1) { n0 = q0; n1 = q1; }
            else {
                n0 = fmul_ftz(cd0, fsub_ftz(1.0f, pzg0));
                n1 = fmul_ftz(cd1, fsub_ftz(1.0f, pzg1));
            }

            // Dual interleaved reductions: A = p_z, Bv = sum(n)
            float A  = fadd_ftz(q0, q1);
            float Bv = fadd_ftz(n0, n1);
#pragma unroll
            for (int m = 16; m > 0; m >>= 1) {
                const float Am = __shfl_xor_sync(FULL_MASK, A,  m);
                const float Bm = __shfl_xor_sync(FULL_MASK, Bv, m);
                A  = fadd_ftz(A,  Am);
                Bv = fadd_ftz(Bv, Bm);
            }

            // Renormalize with the reference's clip (flush on division too)
            const float norm = fmaxf(Bv, 1e-6f);
            cd0 = fdiv_ftz(n0, norm);
            cd1 = fdiv_ftz(n1, norm);

            // KL (output only; continuous path)
            const float l1 = __logf(prob + EPSF);
            const float l0 = __logf((1.0f - prob) + EPSF);
            const float m1 = __logf(A + EPSF);
            const float m0 = __logf((1.0f - A) + EPSF);
            const float kl = prob * (l1 - m1) + (1.0f - prob) * (l0 - m0);
            if (s == lane) mykl = kl;

            csf += s1 ? 1 : 0;
        }
        op[c * 32 + lane] = mykl;
    }
}

extern "C" void kernel_launch(void* const* d_in, const int* in_sizes, int n_in,
                              void* d_out, int out_size) {
    const float* z_pres = (const float*)d_in[0];   // z_pres      [B,1,16,16]
    const float* z_prob = (const float*)d_in[1];   // z_pres_prob [B,1,16,16]
    float*       out    = (float*)d_out;           // obj_kl      [B,1,16,16]
    obj_kl_kernel<<<B, 32>>>(z_pres, z_prob, out);
}

// round 12
// speedup vs baseline: 1.1764x; 1.1764x over previous
#include <cuda_runtime.h>
#include <math.h>

#define FULL_MASK 0xffffffffu

constexpr int HW = 256;   // 16x16 grid -> scan length
constexpr int B  = 1024;

// f32 ops with explicit FTZ semantics, independent of nvcc flags.
// Only used where the reference's flush dynamics affect the STATE.
__device__ __forceinline__ float fmul_ftz(float a, float b) {
    float r; asm("mul.rn.ftz.f32 %0,%1,%2;" : "=f"(r) : "f"(a), "f"(b)); return r;
}
__device__ __forceinline__ float fadd_ftz(float a, float b) {
    float r; asm("add.rn.ftz.f32 %0,%1,%2;" : "=f"(r) : "f"(a), "f"(b)); return r;
}
__device__ __forceinline__ float fdiv_ftz(float a, float b) {
    float r; asm("div.rn.ftz.f32 %0,%1,%2;" : "=f"(r) : "f"(a), "f"(b)); return r;
}

// One warp per batch row. Count support j in [0,64): lane L holds j=L (cd0)
// and j=L+32 (cd1). Init zero for j >= 42 (p^42 dies in the reference's
// approx-pow lowering); afterwards faithful f32-FTZ dynamics reproduce the
// reference's flush-driven death of the posterior exactly.
// pzg = t/denom is reproduced bit-exactly as f32(f64(t) * f64(1/denom)):
// the f64 error 2^-52 is far below the >=2^-33 gap from any t/denom
// (t<=63, denom<=256) to an f32 rounding boundary.
__global__ __launch_bounds__(32)
void obj_kl_kernel(const float* __restrict__ z_pres,
                   const float* __restrict__ z_prob,
                   float* __restrict__ out)
{
    const int b    = blockIdx.x;
    const int lane = threadIdx.x;

    const float* pr = z_prob + b * HW;
    const float* zs = z_pres + b * HW;
    float*       op = out    + b * HW;

    // p in f32 exactly as the reference: 1/(exp(2f)+1)
    const float  e2p1 = 7.3890560989306495f + 1.0f;
    const float  pf   = __fdiv_rn(1.0f, e2p1);
    const double pd   = (double)pf;

    // (1-p)p^lane and (1-p)p^(lane+32), correctly rounded via f64 binary exp.
    double pp = 1.0, ps = pd;
    int e = lane;
#pragma unroll
    for (int k = 0; k < 5; ++k) { if (e & 1) pp *= ps; ps *= ps; e >>= 1; }
    const double omp = 1.0 - pd;
    float cd0 = (float)(omp * pp);                        // j = lane
    float cd1 = (lane <= 9) ? (float)(omp * pp * ps)      // j = lane+32 (<=41)
                            : 0.0f;

    // Faithful init normalization (identical to the passing R7 kernel).
    {
        float S = fadd_ftz(cd0, cd1);
#pragma unroll
        for (int m = 16; m > 0; m >>= 1)
            S = fadd_ftz(S, __shfl_xor_sync(FULL_MASK, S, m));
        cd0 = fdiv_ftz(cd0, S);
        cd1 = fdiv_ftz(cd1, S);
    }

    int  csf   = 0;       // count_so_far at chunk start (integer, exact)
    bool alive = true;
    const float EPSF   = 1e-9f;
    const float LOGEPS = __logf(1e-9f);

#pragma unroll 1
    for (int c = 0; c < 8; ++c) {
        const float myp = pr[c * 32 + lane];
        // per-lane log terms (only lane s's values enter kl at step s)
        const float cl1 = __logf(myp + EPSF);
        const float cl0 = __logf((1.0f - myp) + EPSF);
        const float klDead = myp * (cl1 - LOGEPS) + (1.0f - myp) * cl0;

        if (!alive) { op[c * 32 + lane] = klDead; continue; }

        const float myz = zs[c * 32 + lane];
        // all 32 samples of this chunk in one ballot; csf via popc prefix
        const unsigned smask =
            __ballot_sync(FULL_MASK, rintf(myz) != 0.0f);
        // lane s's reciprocal denominator for step s of this chunk (f64)
        const double inv = 1.0 / (double)(HW - c * 32 - lane);

        float mykl = 0.0f;

#pragma unroll
        for (int h = 0; h < 2; ++h) {
            // Dynamic death check every 16 steps: max live j vs current csf.
            const unsigned bb0 = __ballot_sync(FULL_MASK, cd0 != 0.0f);
            const unsigned bb1 = __ballot_sync(FULL_MASK, cd1 != 0.0f);
            const int maxj = bb1 ? (63 - __clz(bb1))
                                 : (bb0 ? (31 - __clz(bb0)) : -1);
            const int csf_h = csf + (h ? __popc(smask & 0xFFFFu) : 0);
            if (maxj <= csf_h) {           // p_z == 0 forever
                alive = false;
                if ((lane >> 4) >= h) mykl = klDead;
                break;
            }

#pragma unroll
            for (int k = 0; k < 16; ++k) {
                const int s     = h * 16 + k;
                const int sbit  = (smask >> s) & 1;
                const int csf_s = csf + __popc(smask & ((1u << s) - 1u));
                const int denom = HW - c * 32 - s;

                // clamp(j - csf, 0, denom) in exact ints
                const int t0 = min(max(lane      - csf_s, 0), denom);
                const int t1 = min(max(lane + 32 - csf_s, 0), denom);

                // pzg = f32(t * (1/denom)) -- correctly rounded (see header)
                const double invs = __shfl_sync(FULL_MASK, inv, s);
                const float pzg0 = (float)((double)t0 * invs);
                const float pzg1 = (float)((double)t1 * invs);

                // q = cd * pzg (state-affecting when sample=1: exact FTZ)
                const float q0 = fmul_ftz(cd0, pzg0);
                const float q1 = fmul_ftz(cd1, pzg1);

                // n = cd * mult (branchless; sbit is warp-uniform)
                const float n0 = sbit ? q0 : fmul_ftz(cd0, 1.0f - pzg0);
                const float n1 = sbit ? q1 : fmul_ftz(cd1, 1.0f - pzg1);

                // dual butterfly reduction: A = p_z, Bv = sum(n)
                float A  = q0 + q1;
                float Bv = n0 + n1;
#pragma unroll
                for (int m = 16; m > 0; m >>= 1) {
                    A  += __shfl_xor_sync(FULL_MASK, A,  m);
                    Bv += __shfl_xor_sync(FULL_MASK, Bv, m);
                }

                // renormalize with the reference's clip (FTZ-exact division)
                const float norm = fmaxf(Bv, 1e-6f);
                cd0 = fdiv_ftz(n0, norm);
                cd1 = fdiv_ftz(n1, norm);

                // KL (output only; continuous)
                const float m1 = __logf(A + EPSF);
                const float m0 = __logf((1.0f - A) + EPSF);
                const float kl = myp * (cl1 - m1) + (1.0f - myp) * (cl0 - m0);
                if (s == lane) mykl = kl;
            }
        }
        csf += __popc(smask);
        op[c * 32 + lane] = mykl;
    }
}

extern "C" void kernel_launch(void* const* d_in, const int* in_sizes, int n_in,
                              void* d_out, int out_size) {
    const float* z_pres = (const float*)d_in[0];   // z_pres      [B,1,16,16]
    const float* z_prob = (const float*)d_in[1];   // z_pres_prob [B,1,16,16]
    float*       out    = (float*)d_out;           // obj_kl      [B,1,16,16]
    obj_kl_kernel<<<B, 32>>>(z_pres, z_prob, out);
}

// round 14
// speedup vs baseline: 3.5372x; 3.0069x over previous
#include <cuda_runtime.h>
#include <math.h>

#define FULL_MASK 0xffffffffu

constexpr int HW = 256;   // 16x16 grid -> scan length
constexpr int B  = 1024;

// f32 ops with explicit FTZ semantics (state-affecting products / init).
__device__ __forceinline__ float fmul_ftz(float a, float b) {
    float r; asm("mul.rn.ftz.f32 %0,%1,%2;" : "=f"(r) : "f"(a), "f"(b)); return r;
}
__device__ __forceinline__ float fadd_ftz(float a, float b) {
    float r; asm("add.rn.ftz.f32 %0,%1,%2;" : "=f"(r) : "f"(a), "f"(b)); return r;
}
__device__ __forceinline__ float fdiv_ftz(float a, float b) {
    float r; asm("div.rn.ftz.f32 %0,%1,%2;" : "=f"(r) : "f"(a), "f"(b)); return r;
}
__device__ __forceinline__ float rcp_approx(float x) {
    float r; asm("rcp.approx.ftz.f32 %0, %1;" : "=f"(r) : "f"(x)); return r;
}
__device__ __forceinline__ float fma_ftz(float a, float b, float c) {
    float r; asm("fma.rn.ftz.f32 %0,%1,%2,%3;" : "=f"(r) : "f"(a), "f"(b), "f"(c));
    return r;
}

// Correctly-rounded n/d (d normal, shared refined reciprocal y1), with the
// final op flushing a denormal quotient to zero -- div.rn.ftz semantics for
// our proven operand range (n in {0} U [2^-126, ~1], d in [1e-6, 1+eps]).
__device__ __forceinline__ float div_corr_ftz(float n, float d, float y1) {
    const float q0  = __fmul_rn(n, y1);          // non-ftz: keep denormals
    const float rem = __fmaf_rn(-q0, d, n);      // exact residual
    return fma_ftz(rem, y1, q0);                 // RN result, flush-if-denormal
}

// pzg = RN(t/d) for integer-valued t in [0,d], d in [1,256], given r = RN(1/d).
// The residual is FMA-exact and t/d can never be an f32 rounding tie, so one
// Markstein correction yields the correctly rounded quotient.
__device__ __forceinline__ float int_div_exact(float t, float d, float r) {
    const float a   = __fmul_rn(t, r);
    const float rem = __fmaf_rn(-a, d, t);
    return __fmaf_rn(rem, r, a);
}

// One warp per batch row. Count support j in [0,64): lane L holds j=L (cd0)
// and j=L+32 (cd1). Init zero for j >= 42 (reference's approx-pow flush);
// afterwards faithful f32-FTZ dynamics reproduce the reference's flush-driven
// death of the posterior exactly. Once max live j <= csf, p_z == 0 forever.
__global__ __launch_bounds__(32)
void obj_kl_kernel(const float* __restrict__ z_pres,
                   const float* __restrict__ z_prob,
                   float* __restrict__ out)
{
    const int b    = blockIdx.x;
    const int lane = threadIdx.x;

    const float* pr = z_prob + b * HW;
    const float* zs = z_pres + b * HW;
    float*       op = out    + b * HW;

    // p in f32 exactly as the reference: 1/(exp(2f)+1)
    const float  e2p1 = 7.3890560989306495f + 1.0f;
    const float  pf   = __fdiv_rn(1.0f, e2p1);
    const double pd   = (double)pf;

    // (1-p)p^lane and (1-p)p^(lane+32) via f64 binary exp (init only).
    double pp = 1.0, ps = pd;
    int e = lane;
#pragma unroll
    for (int k = 0; k < 5; ++k) { if (e & 1) pp *= ps; ps *= ps; e >>= 1; }
    const double omp = 1.0 - pd;
    float cd0 = (float)(omp * pp);                        // j = lane
    float cd1 = (lane <= 9) ? (float)(omp * pp * ps)      // j = lane+32 (<=41)
                            : 0.0f;

    // Faithful init normalization (identical to R7/R8 passing kernels).
    {
        float S = fadd_ftz(cd0, cd1);
#pragma unroll
        for (int m = 16; m > 0; m >>= 1)
            S = fadd_ftz(S, __shfl_xor_sync(FULL_MASK, S, m));
        cd0 = fdiv_ftz(cd0, S);
        cd1 = fdiv_ftz(cd1, S);
    }

    int  csf   = 0;       // count_so_far at chunk start (integer, exact)
    bool alive = true;
    const float EPSF   = 1e-9f;
    const float LOGEPS = __logf(1e-9f);
    const float lanef  = (float)lane;

#pragma unroll 1
    for (int c = 0; c < 8; ++c) {
        const float myp = pr[c * 32 + lane];
        const float cl1 = __logf(myp + EPSF);
        const float cl0 = __logf((1.0f - myp) + EPSF);
        const float klDead = myp * (cl1 - LOGEPS) + (1.0f - myp) * cl0;

        if (!alive) { op[c * 32 + lane] = klDead; continue; }

        const float myz = zs[c * 32 + lane];
        const unsigned smask = __ballot_sync(FULL_MASK, rintf(myz) != 0.0f);

        const float basef = (float)(HW - c * 32);
        // per-lane: correctly-rounded reciprocal for step s = lane (off-chain)
        const float rv = __fdiv_rn(1.0f, basef - lanef);

        float mykl = 0.0f;

#pragma unroll
        for (int h = 0; h < 2; ++h) {
            // Death / mode check every 16 steps.
            const unsigned bb0 = __ballot_sync(FULL_MASK, cd0 != 0.0f);
            const unsigned bb1 = __ballot_sync(FULL_MASK, cd1 != 0.0f);
            const int maxj = bb1 ? (63 - __clz(bb1))
                                 : (bb0 ? (31 - __clz(bb0)) : -1);
            const int csf_h = csf + (h ? __popc(smask & 0xFFFFu) : 0);
            if (maxj <= csf_h) {           // p_z == 0 forever
                alive = false;
                if ((lane >> 4) >= h) mykl = klDead;
                break;
            }

            const bool heavy = (bb1 != 0);

#pragma unroll
            for (int k = 0; k < 16; ++k) {
                const int s = h * 16 + k;
                const int sbit = (smask >> s) & 1;          // warp-uniform
                // csf before step s -- uniform popc, no shuffle needed
                const float csff =
                    (float)(csf + __popc(smask & ((1u << s) - 1u)));
                const float denf = basef - (float)s;
                const float r    = __shfl_sync(FULL_MASK, rv, s);

                const float t0 = fminf(fmaxf(lanef - csff, 0.0f), denf);
                const float pzg0 = int_div_exact(t0, denf, r);
                const float q0 = fmul_ftz(cd0, pzg0);

                float q1 = 0.0f, pzg1 = 0.0f;
                if (heavy) {
                    const float t1 =
                        fminf(fmaxf(lanef + 32.0f - csff, 0.0f), denf);
                    pzg1 = int_div_exact(t1, denf, r);
                    q1   = fmul_ftz(cd1, pzg1);
                }

                // A = p_z reduction (always); Bv only needed when sample=0
                float A = heavy ? (q0 + q1) : q0;
                float n0, n1 = 0.0f, Bv;
                if (sbit) {
#pragma unroll
                    for (int m = 16; m > 0; m >>= 1)
                        A += __shfl_xor_sync(FULL_MASK, A, m);
                    n0 = q0; n1 = q1;
                    Bv = A;                     // bit-identical to sum(n)
                } else {
                    n0 = fmul_ftz(cd0, 1.0f - pzg0);
                    if (heavy) n1 = fmul_ftz(cd1, 1.0f - pzg1);
                    Bv = heavy ? (n0 + n1) : n0;
#pragma unroll
                    for (int m = 16; m > 0; m >>= 1) {
                        A  += __shfl_xor_sync(FULL_MASK, A,  m);
                        Bv += __shfl_xor_sync(FULL_MASK, Bv, m);
                    }
                }

                // renormalize: shared refined reciprocal, flush-exact division
                const float norm = fmaxf(Bv, 1e-6f);
                const float y0 = rcp_approx(norm);
                const float ee = __fmaf_rn(-norm, y0, 1.0f);
                const float y1 = __fmaf_rn(y0, ee, y0);
                cd0 = div_corr_ftz(n0, norm, y1);
                if (heavy) cd1 = div_corr_ftz(n1, norm, y1);

                // KL (output only; continuous)
                const float m1 = __logf(A + EPSF);
                const float m0 = __logf((1.0f - A) + EPSF);
                const float kl = myp * (cl1 - m1) + (1.0f - myp) * (cl0 - m0);
                if (s == lane) mykl = kl;
            }
        }
        csf += __popc(smask);
        op[c * 32 + lane] = mykl;
    }
}

extern "C" void kernel_launch(void* const* d_in, const int* in_sizes, int n_in,
                              void* d_out, int out_size) {
    const float* z_pres = (const float*)d_in[0];   // z_pres      [B,1,16,16]
    const float* z_prob = (const float*)d_in[1];   // z_pres_prob [B,1,16,16]
    float*       out    = (float*)d_out;           // obj_kl      [B,1,16,16]
    obj_kl_kernel<<<B, 32>>>(z_pres, z_prob, out);
}